// round 2
// baseline (speedup 1.0000x reference)
#include <cuda_runtime.h>
#include <cstdint>

typedef unsigned long long ull;

#define NPX 262144   // 4*256*256 pixels

// Conv outputs, transposed [d][px] (static __device__: allocation-guard safe)
__device__ float g_cmt[(size_t)64 * NPX];
__device__ float g_crt[(size_t)64 * NPX];

// ---------------- packed f32x2 helpers ----------------
__device__ __forceinline__ ull fma2(ull a, ull b, ull c) {
    ull d;
    asm("fma.rn.f32x2 %0, %1, %2, %3;" : "=l"(d) : "l"(a), "l"(b), "l"(c));
    return d;
}
__device__ __forceinline__ ull mul2(ull a, ull b) {
    ull d;
    asm("mul.rn.f32x2 %0, %1, %2;" : "=l"(d) : "l"(a), "l"(b));
    return d;
}
__device__ __forceinline__ ull pack2(float x, float y) {
    ull r;
    asm("mov.b64 %0, {%1, %2};" : "=l"(r) : "f"(x), "f"(y));
    return r;
}
__device__ __forceinline__ float2 unpack2(ull v) {
    float2 r;
    asm("mov.b64 {%0, %1}, %2;" : "=f"(r.x), "=f"(r.y) : "l"(v));
    return r;
}

// ---------------- conv kernel: C = A[M,64] * W[64,64], output transposed [d][px] ----------------
__global__ void __launch_bounds__(128) conv_kernel(
    const float* __restrict__ main_in, const float* __restrict__ ref_in,
    const float* __restrict__ Wm, const float* __restrict__ Wr)
{
    __shared__ float As[128 * 64];   // [m][c], column XOR-swizzled by (m>>3)&3
    __shared__ float Ws[64 * 64];    // [k][d]

    const float* A = blockIdx.y ? ref_in : main_in;
    const float* W = blockIdx.y ? Wr : Wm;
    float* gt      = blockIdx.y ? g_crt : g_cmt;

    int t = threadIdx.x;
    size_t bM = (size_t)blockIdx.x * 128;

    const float4* Ag = (const float4*)(A + bM * 64);
#pragma unroll
    for (int i = 0; i < 16; i++) {
        int idx = i * 128 + t;
        float4 v = Ag[idx];
        int ml = idx >> 4;
        int c0 = (idx & 15) * 4;
        int s = ml & 24;
        As[ml * 64 + ((c0 + 0) ^ s)] = v.x;
        As[ml * 64 + ((c0 + 1) ^ s)] = v.y;
        As[ml * 64 + ((c0 + 2) ^ s)] = v.z;
        As[ml * 64 + ((c0 + 3) ^ s)] = v.w;
    }
    const float4* Wg4 = (const float4*)W;
    float4* Ws4 = (float4*)Ws;
#pragma unroll
    for (int i = 0; i < 8; i++)
        Ws4[i * 128 + t] = Wg4[i * 128 + t];

    __syncthreads();

    int tn = t & 7;
    int tm = t >> 3;
    int sw = (tm & 3) << 3;

    ull acc[8][4];
#pragma unroll
    for (int p = 0; p < 8; p++)
#pragma unroll
        for (int j = 0; j < 4; j++) acc[p][j] = 0ull;

    const float* arow = &As[(tm * 8) * 64];

#pragma unroll 8
    for (int k = 0; k < 64; k++) {
        int sk = k ^ sw;
        ulonglong2 w01 = *(const ulonglong2*)&Ws[k * 64 + tn * 4];
        ulonglong2 w23 = *(const ulonglong2*)&Ws[k * 64 + 32 + tn * 4];
        ull av[8];
#pragma unroll
        for (int p = 0; p < 8; p++) {
            float a = arow[p * 64 + sk];
            av[p] = pack2(a, a);
        }
#pragma unroll
        for (int p = 0; p < 8; p++) {
            acc[p][0] = fma2(av[p], w01.x, acc[p][0]);
            acc[p][1] = fma2(av[p], w01.y, acc[p][1]);
            acc[p][2] = fma2(av[p], w23.x, acc[p][2]);
            acc[p][3] = fma2(av[p], w23.y, acc[p][3]);
        }
    }

    // Transposed epilogue: [d][px]
    size_t pxb = bM + tm * 8;
    int dbase[4] = { tn * 4, tn * 4 + 2, 32 + tn * 4, 32 + tn * 4 + 2 };
#pragma unroll
    for (int j = 0; j < 4; j++) {
        float2 f[8];
#pragma unroll
        for (int p = 0; p < 8; p++) f[p] = unpack2(acc[p][j]);
        float* o0 = gt + (size_t)dbase[j] * NPX + pxb;
        float* o1 = o0 + (size_t)NPX;
        *(float4*)o0       = make_float4(f[0].x, f[1].x, f[2].x, f[3].x);
        *(float4*)(o0 + 4) = make_float4(f[4].x, f[5].x, f[6].x, f[7].x);
        *(float4*)o1       = make_float4(f[0].y, f[1].y, f[2].y, f[3].y);
        *(float4*)(o1 + 4) = make_float4(f[4].y, f[5].y, f[6].y, f[7].y);
    }
}

// ---------------- attention kernel v2: pixel-packed ----------------
// Tile 32 wide x 16 tall = 512 px, 128 threads, 4-px horizontal strip per thread.
// crs: per-channel float planes [16 ch][20 rows][36 cols], chunked over 4 channel groups.
#define TW 32
#define TH 16
#define HW 36
#define HH 20
#define CCH 16
#define PLANE 720   // HH*HW

__global__ void __launch_bounds__(128, 3) attn2_kernel(
    const float* __restrict__ Wg, float* __restrict__ out)
{
    extern __shared__ float smem[];
    float* crs = smem;                   // 16*720 floats = 46,080 B
    float* Wgs = smem + CCH * PLANE;     // 1600 floats   =  6,400 B

    int t = threadIdx.x;
    int bx = blockIdx.x, by = blockIdx.y, b = blockIdx.z;
    int strip = t & 7, row = t >> 3;
    int x0 = strip * 4;
    int gy = by * TH + row;
    int gx0 = bx * TW + x0;
    size_t px0 = ((size_t)b * 256 + gy) * 256 + gx0;

    for (int i = t; i < 1600; i += 128) Wgs[i] = Wg[i];

    ull acc[50];   // [kk][lane]: lane0=(px0,px1), lane1=(px2,px3)
#pragma unroll
    for (int i = 0; i < 50; i++) acc[i] = 0ull;

    int y0t = by * TH - 2;

    for (int cc = 0; cc < 4; cc++) {
        if (cc) __syncthreads();
        // ---- fill halo planes (float4 jobs: 16 ch * 20 rows * 10 quads) ----
        for (int f = t; f < CCH * HH * 10; f += 128) {
            int q = f % 10;
            int rh = f / 10;
            int hy = rh % HH;
            int c = rh / HH;
            int gyh = y0t + hy;
            int gxb = bx * TW - 4 + q * 4;      // 16B-aligned gmem base
            float vv[4] = {0.f, 0.f, 0.f, 0.f};
            bool rok = (gyh >= 0) && (gyh < 256);
            if (rok) {
                const float* pl = g_crt + (size_t)(cc * CCH + c) * NPX
                                        + ((size_t)b * 256 + gyh) * 256;
                if (gxb >= 0 && gxb + 3 < 256) {
                    float4 v = *(const float4*)(pl + gxb);
                    vv[0] = v.x; vv[1] = v.y; vv[2] = v.z; vv[3] = v.w;
                } else {
#pragma unroll
                    for (int j = 0; j < 4; j++) {
                        int gx = gxb + j;
                        if (gx >= 0 && gx < 256) vv[j] = pl[gx];
                    }
                }
            }
            int sxb = q * 4 - 2;
            float* dst = &crs[c * PLANE + hy * HW];
#pragma unroll
            for (int j = 0; j < 4; j++) {
                int sx = sxb + j;
                if (sx >= 0 && sx < HW) dst[sx] = vv[j];
            }
        }
        __syncthreads();

        // ---- accumulate logits for this channel chunk ----
        const float* cmp = g_cmt + (size_t)(cc * CCH) * NPX + px0;
        ulonglong2 cm = *(const ulonglong2*)cmp;      // prefetch c=0
#pragma unroll 2
        for (int c = 0; c < CCH; c++) {
            ull a01 = cm.x, a23 = cm.y;
            if (c + 1 < CCH)
                cm = *(const ulonglong2*)(cmp + (size_t)(c + 1) * NPX);
            const float* cr = &crs[c * PLANE + row * HW + x0];
#pragma unroll
            for (int r = 0; r < 5; r++) {
                float4 fa = *(const float4*)(cr + r * HW);
                float4 fb = *(const float4*)(cr + r * HW + 4);
                ull q0 = pack2(fa.x, fa.y), q1 = pack2(fa.z, fa.w);
                ull q2 = pack2(fb.x, fb.y), q3 = pack2(fb.z, fb.w);
                ull u1 = pack2(fa.y, fa.z), u2 = pack2(fa.w, fb.x), u3 = pack2(fb.y, fb.z);
                int k0 = r * 10;   // (r*5+kx)*2 + lane
                acc[k0 + 0] = fma2(a01, q0, acc[k0 + 0]);
                acc[k0 + 1] = fma2(a23, q1, acc[k0 + 1]);
                acc[k0 + 2] = fma2(a01, u1, acc[k0 + 2]);
                acc[k0 + 3] = fma2(a23, u2, acc[k0 + 3]);
                acc[k0 + 4] = fma2(a01, q1, acc[k0 + 4]);
                acc[k0 + 5] = fma2(a23, q2, acc[k0 + 5]);
                acc[k0 + 6] = fma2(a01, u2, acc[k0 + 6]);
                acc[k0 + 7] = fma2(a23, u3, acc[k0 + 7]);
                acc[k0 + 8] = fma2(a01, q2, acc[k0 + 8]);
                acc[k0 + 9] = fma2(a23, q3, acc[k0 + 9]);
            }
        }
    }

    // ---- softmax over 25 (per pixel lane) ----
#pragma unroll
    for (int l = 0; l < 2; l++) {
        float mA = -1e30f, mB = -1e30f;
#pragma unroll
        for (int kk = 0; kk < 25; kk++) {
            float2 v = unpack2(acc[kk * 2 + l]);
            mA = fmaxf(mA, v.x); mB = fmaxf(mB, v.y);
        }
        float sA = 0.f, sB = 0.f;
#pragma unroll
        for (int kk = 0; kk < 25; kk++) {
            float2 v = unpack2(acc[kk * 2 + l]);
            float eA = __expf(v.x - mA), eB = __expf(v.y - mB);
            sA += eA; sB += eB;
            acc[kk * 2 + l] = pack2(eA, eB);
        }
        ull iv = pack2(__fdividef(1.f, sA), __fdividef(1.f, sB));
#pragma unroll
        for (int kk = 0; kk < 25; kk++)
            acc[kk * 2 + l] = mul2(acc[kk * 2 + l], iv);
    }

    // ---- out = attn @ Wg, d-chunked (8 d per chunk), 4 px together ----
    float* op = out + px0 * 64;
#pragma unroll 1
    for (int dc = 0; dc < 8; dc++) {
        ull o[4][4];
#pragma unroll
        for (int p = 0; p < 4; p++)
#pragma unroll
            for (int j = 0; j < 4; j++) o[p][j] = 0ull;
#pragma unroll
        for (int kk = 0; kk < 25; kk++) {
            ulonglong2 w01 = *(const ulonglong2*)&Wgs[kk * 64 + dc * 8];
            ulonglong2 w23 = *(const ulonglong2*)&Wgs[kk * 64 + dc * 8 + 4];
            float2 pA = unpack2(acc[kk * 2 + 0]);
            float2 pB = unpack2(acc[kk * 2 + 1]);
            ull s0 = pack2(pA.x, pA.x), s1 = pack2(pA.y, pA.y);
            ull s2 = pack2(pB.x, pB.x), s3 = pack2(pB.y, pB.y);
            o[0][0] = fma2(s0, w01.x, o[0][0]); o[0][1] = fma2(s0, w01.y, o[0][1]);
            o[0][2] = fma2(s0, w23.x, o[0][2]); o[0][3] = fma2(s0, w23.y, o[0][3]);
            o[1][0] = fma2(s1, w01.x, o[1][0]); o[1][1] = fma2(s1, w01.y, o[1][1]);
            o[1][2] = fma2(s1, w23.x, o[1][2]); o[1][3] = fma2(s1, w23.y, o[1][3]);
            o[2][0] = fma2(s2, w01.x, o[2][0]); o[2][1] = fma2(s2, w01.y, o[2][1]);
            o[2][2] = fma2(s2, w23.x, o[2][2]); o[2][3] = fma2(s2, w23.y, o[2][3]);
            o[3][0] = fma2(s3, w01.x, o[3][0]); o[3][1] = fma2(s3, w01.y, o[3][1]);
            o[3][2] = fma2(s3, w23.x, o[3][2]); o[3][3] = fma2(s3, w23.y, o[3][3]);
        }
#pragma unroll
        for (int p = 0; p < 4; p++) {
            float2 a = unpack2(o[p][0]), b2 = unpack2(o[p][1]);
            float2 c2 = unpack2(o[p][2]), d2 = unpack2(o[p][3]);
            float* dst = op + p * 64 + dc * 8;
            *(float4*)dst       = make_float4(a.x, a.y, b2.x, b2.y);
            *(float4*)(dst + 4) = make_float4(c2.x, c2.y, d2.x, d2.y);
        }
    }
}

// ---------------- launch ----------------
extern "C" void kernel_launch(void* const* d_in, const int* in_sizes, int n_in,
                              void* d_out, int out_size)
{
    const float* main_in = (const float*)d_in[0];
    const float* ref_in  = (const float*)d_in[1];
    const float* Wm      = (const float*)d_in[2];
    const float* Wr      = (const float*)d_in[3];
    const float* Wg      = (const float*)d_in[4];
    float* out = (float*)d_out;

    conv_kernel<<<dim3(2048, 2), 128>>>(main_in, ref_in, Wm, Wr);

    const int smem_bytes = (CCH * PLANE + 1600) * 4;  // 52,480 B
    cudaFuncSetAttribute(attn2_kernel, cudaFuncAttributeMaxDynamicSharedMemorySize, smem_bytes);

    attn2_kernel<<<dim3(8, 16, 4), 128, smem_bytes>>>(Wg, out);
}

// round 3
// speedup vs baseline: 1.2375x; 1.2375x over previous
#include <cuda_runtime.h>
#include <cstdint>

typedef unsigned long long ull;

#define NPX 262144   // 4*256*256 pixels

// Conv outputs, transposed [d][px] (static __device__: allocation-guard safe)
__device__ float g_cmt[(size_t)64 * NPX];
__device__ float g_crt[(size_t)64 * NPX];

// ---------------- packed f32x2 helpers ----------------
__device__ __forceinline__ ull fma2(ull a, ull b, ull c) {
    ull d;
    asm("fma.rn.f32x2 %0, %1, %2, %3;" : "=l"(d) : "l"(a), "l"(b), "l"(c));
    return d;
}
__device__ __forceinline__ ull mul2(ull a, ull b) {
    ull d;
    asm("mul.rn.f32x2 %0, %1, %2;" : "=l"(d) : "l"(a), "l"(b));
    return d;
}
__device__ __forceinline__ ull pack2(float x, float y) {
    ull r;
    asm("mov.b64 %0, {%1, %2};" : "=l"(r) : "f"(x), "f"(y));
    return r;
}
__device__ __forceinline__ float2 unpack2(ull v) {
    float2 r;
    asm("mov.b64 {%0, %1}, %2;" : "=f"(r.x), "=f"(r.y) : "l"(v));
    return r;
}

// ---------------- conv kernel: C = A[M,64] * W[64,64], output transposed [d][px] ----------------
__global__ void __launch_bounds__(128) conv_kernel(
    const float* __restrict__ main_in, const float* __restrict__ ref_in,
    const float* __restrict__ Wm, const float* __restrict__ Wr)
{
    __shared__ float As[128 * 64];   // [m][c], column XOR-swizzled by (m>>3)&3
    __shared__ float Ws[64 * 64];    // [k][d]

    const float* A = blockIdx.y ? ref_in : main_in;
    const float* W = blockIdx.y ? Wr : Wm;
    float* gt      = blockIdx.y ? g_crt : g_cmt;

    int t = threadIdx.x;
    size_t bM = (size_t)blockIdx.x * 128;

    const float4* Ag = (const float4*)(A + bM * 64);
#pragma unroll
    for (int i = 0; i < 16; i++) {
        int idx = i * 128 + t;
        float4 v = Ag[idx];
        int ml = idx >> 4;
        int c0 = (idx & 15) * 4;
        int s = ml & 24;
        As[ml * 64 + ((c0 + 0) ^ s)] = v.x;
        As[ml * 64 + ((c0 + 1) ^ s)] = v.y;
        As[ml * 64 + ((c0 + 2) ^ s)] = v.z;
        As[ml * 64 + ((c0 + 3) ^ s)] = v.w;
    }
    const float4* Wg4 = (const float4*)W;
    float4* Ws4 = (float4*)Ws;
#pragma unroll
    for (int i = 0; i < 8; i++)
        Ws4[i * 128 + t] = Wg4[i * 128 + t];

    __syncthreads();

    int tn = t & 7;
    int tm = t >> 3;
    int sw = (tm & 3) << 3;

    ull acc[8][4];
#pragma unroll
    for (int p = 0; p < 8; p++)
#pragma unroll
        for (int j = 0; j < 4; j++) acc[p][j] = 0ull;

    const float* arow = &As[(tm * 8) * 64];

#pragma unroll 8
    for (int k = 0; k < 64; k++) {
        int sk = k ^ sw;
        ulonglong2 w01 = *(const ulonglong2*)&Ws[k * 64 + tn * 4];
        ulonglong2 w23 = *(const ulonglong2*)&Ws[k * 64 + 32 + tn * 4];
        ull av[8];
#pragma unroll
        for (int p = 0; p < 8; p++) {
            float a = arow[p * 64 + sk];
            av[p] = pack2(a, a);
        }
#pragma unroll
        for (int p = 0; p < 8; p++) {
            acc[p][0] = fma2(av[p], w01.x, acc[p][0]);
            acc[p][1] = fma2(av[p], w01.y, acc[p][1]);
            acc[p][2] = fma2(av[p], w23.x, acc[p][2]);
            acc[p][3] = fma2(av[p], w23.y, acc[p][3]);
        }
    }

    size_t pxb = bM + tm * 8;
    int dbase[4] = { tn * 4, tn * 4 + 2, 32 + tn * 4, 32 + tn * 4 + 2 };
#pragma unroll
    for (int j = 0; j < 4; j++) {
        float2 f[8];
#pragma unroll
        for (int p = 0; p < 8; p++) f[p] = unpack2(acc[p][j]);
        float* o0 = gt + (size_t)dbase[j] * NPX + pxb;
        float* o1 = o0 + (size_t)NPX;
        *(float4*)o0       = make_float4(f[0].x, f[1].x, f[2].x, f[3].x);
        *(float4*)(o0 + 4) = make_float4(f[4].x, f[5].x, f[6].x, f[7].x);
        *(float4*)o1       = make_float4(f[0].y, f[1].y, f[2].y, f[3].y);
        *(float4*)(o1 + 4) = make_float4(f[4].y, f[5].y, f[6].y, f[7].y);
    }
}

// ---------------- attention kernel v3: 2 px/thread, 256 threads ----------------
// Tile 32 wide x 16 tall = 512 px, thread = 2-px horizontal pair.
// crs: per-channel halo planes [16 ch][20 rows][40 cols] (col 0 == gx bx*32-2).
// ps (unioned with crs): softmax probs [25][520].
#define TW 32
#define TH 16
#define HH 20
#define HWS 40
#define CCH 16
#define PLANE 800          // HH*HWS
#define PSS 520
#define UNION_FLOATS 13000 // max(16*800=12800, 25*520=13000)

__global__ void __launch_bounds__(256, 2) attn3_kernel(
    const float* __restrict__ Wg, float* __restrict__ out)
{
    extern __shared__ float smem[];
    float* crs = smem;                    // halo planes (logit phase)
    float* ps  = smem;                    // probs [25][520] (out phase, unioned)
    float* Wgs = smem + UNION_FLOATS;     // 1600 floats

    int t = threadIdx.x;
    int bx = blockIdx.x, by = blockIdx.y, b = blockIdx.z;
    int strip = t & 15, row = t >> 4;
    int x0 = strip * 2;
    int gy = by * TH + row;
    int gx0 = bx * TW + x0;
    size_t px0g = ((size_t)b * 256 + gy) * 256 + gx0;
    int lp0 = row * TW + x0;              // local pixel id of pair base

    for (int i = t; i < 1600; i += 256) Wgs[i] = Wg[i];

    ull acc[25];
#pragma unroll
    for (int i = 0; i < 25; i++) acc[i] = 0ull;

    int y0t = by * TH - 2;

    for (int cc = 0; cc < 4; cc++) {
        __syncthreads();
        // ---- fill halo planes: jobs = 16 ch * 20 rows * 10 quads ----
        for (int f = t; f < CCH * HH * 10; f += 256) {
            int q = f % 10;
            int rh = f / 10;
            int hy = rh % HH;
            int c = rh / HH;
            int gyh = y0t + hy;
            int gxb = bx * TW - 4 + q * 4;     // 16B-aligned gmem base
            float vv[4] = {0.f, 0.f, 0.f, 0.f};
            if (gyh >= 0 && gyh < 256) {
                const float* pl = g_crt + (size_t)(cc * CCH + c) * NPX
                                        + ((size_t)b * 256 + gyh) * 256;
                if (gxb >= 0 && gxb + 3 < 256) {
                    float4 v = *(const float4*)(pl + gxb);
                    vv[0] = v.x; vv[1] = v.y; vv[2] = v.z; vv[3] = v.w;
                } else {
#pragma unroll
                    for (int j = 0; j < 4; j++) {
                        int gx = gxb + j;
                        if (gx >= 0 && gx < 256) vv[j] = pl[gx];
                    }
                }
            }
            float* dst = &crs[c * PLANE + hy * HWS];
#pragma unroll
            for (int j = 0; j < 4; j++) {
                int sx = q * 4 + j - 2;        // col = gx - (bx*TW - 2)
                if (sx >= 0 && sx < 36) dst[sx] = vv[j];
            }
        }
        __syncthreads();

        // ---- accumulate logits ----
        const float* cmp = g_cmt + (size_t)(cc * CCH) * NPX + px0g;
        ull cm2 = *(const ull*)cmp;
#pragma unroll 4
        for (int c = 0; c < CCH; c++) {
            ull cur = cm2;
            if (c + 1 < CCH)
                cm2 = *(const ull*)(cmp + (size_t)(c + 1) * NPX);
            const float* cr = &crs[c * PLANE + row * HWS + x0];
#pragma unroll
            for (int r = 0; r < 5; r++) {
                float2 A = *(const float2*)(cr + r * HWS);
                float2 B = *(const float2*)(cr + r * HWS + 2);
                float2 C = *(const float2*)(cr + r * HWS + 4);
                ull k0 = pack2(A.x, A.y);
                ull k1 = pack2(A.y, B.x);
                ull k2 = pack2(B.x, B.y);
                ull k3 = pack2(B.y, C.x);
                ull k4 = pack2(C.x, C.y);
                acc[r * 5 + 0] = fma2(cur, k0, acc[r * 5 + 0]);
                acc[r * 5 + 1] = fma2(cur, k1, acc[r * 5 + 1]);
                acc[r * 5 + 2] = fma2(cur, k2, acc[r * 5 + 2]);
                acc[r * 5 + 3] = fma2(cur, k3, acc[r * 5 + 3]);
                acc[r * 5 + 4] = fma2(cur, k4, acc[r * 5 + 4]);
            }
        }
    }

    // ---- softmax over 25 (lanes = the two pixels) ----
    {
        float mA = -1e30f, mB = -1e30f;
#pragma unroll
        for (int kk = 0; kk < 25; kk++) {
            float2 v = unpack2(acc[kk]);
            mA = fmaxf(mA, v.x); mB = fmaxf(mB, v.y);
        }
        float sA = 0.f, sB = 0.f;
#pragma unroll
        for (int kk = 0; kk < 25; kk++) {
            float2 v = unpack2(acc[kk]);
            float eA = __expf(v.x - mA), eB = __expf(v.y - mB);
            sA += eA; sB += eB;
            acc[kk] = pack2(eA, eB);
        }
        ull iv = pack2(__fdividef(1.f, sA), __fdividef(1.f, sB));
#pragma unroll
        for (int kk = 0; kk < 25; kk++)
            acc[kk] = mul2(acc[kk], iv);
    }

    // ---- transpose probs to smem: ps[kk][lp] (overwrites crs) ----
    __syncthreads();
#pragma unroll
    for (int kk = 0; kk < 25; kk++)
        *(ull*)&ps[kk * PSS + lp0] = acc[kk];
    __syncthreads();

    // ---- out = attn @ Wg: warp w -> 64 px, lane l -> d=l and d=l+32 ----
    {
        int w = t >> 5, l = t & 31;
        ull wr0[25], wr1[25];
#pragma unroll
        for (int kk = 0; kk < 25; kk++) {
            float w0 = Wgs[kk * 64 + l];
            float w1 = Wgs[kk * 64 + 32 + l];
            wr0[kk] = pack2(w0, w0);
            wr1[kk] = pack2(w1, w1);
        }
#pragma unroll 1
        for (int i = 0; i < 16; i++) {
            int lpa = w * 64 + i * 4;
            int lpb = lpa + 2;
            int ra = lpa >> 5, ca = lpa & 31;
            int rb = lpb >> 5, cb = lpb & 31;
            size_t ga = ((size_t)b * 256 + by * TH + ra) * 256 + bx * TW + ca;
            size_t gb = ((size_t)b * 256 + by * TH + rb) * 256 + bx * TW + cb;
            ull oa0 = 0, oa1 = 0, ob0 = 0, ob1 = 0;
#pragma unroll
            for (int kk = 0; kk < 25; kk++) {
                ull pa = *(const ull*)&ps[kk * PSS + lpa];
                ull pb = *(const ull*)&ps[kk * PSS + lpb];
                oa0 = fma2(pa, wr0[kk], oa0);
                oa1 = fma2(pa, wr1[kk], oa1);
                ob0 = fma2(pb, wr0[kk], ob0);
                ob1 = fma2(pb, wr1[kk], ob1);
            }
            float2 a0 = unpack2(oa0), a1 = unpack2(oa1);
            float2 b0 = unpack2(ob0), b1 = unpack2(ob1);
            out[ga * 64 + l]            = a0.x;
            out[(ga + 1) * 64 + l]      = a0.y;
            out[ga * 64 + 32 + l]       = a1.x;
            out[(ga + 1) * 64 + 32 + l] = a1.y;
            out[gb * 64 + l]            = b0.x;
            out[(gb + 1) * 64 + l]      = b0.y;
            out[gb * 64 + 32 + l]       = b1.x;
            out[(gb + 1) * 64 + 32 + l] = b1.y;
        }
    }
}

// ---------------- launch ----------------
extern "C" void kernel_launch(void* const* d_in, const int* in_sizes, int n_in,
                              void* d_out, int out_size)
{
    const float* main_in = (const float*)d_in[0];
    const float* ref_in  = (const float*)d_in[1];
    const float* Wm      = (const float*)d_in[2];
    const float* Wr      = (const float*)d_in[3];
    const float* Wg      = (const float*)d_in[4];
    float* out = (float*)d_out;

    conv_kernel<<<dim3(2048, 2), 128>>>(main_in, ref_in, Wm, Wr);

    const int smem_bytes = (UNION_FLOATS + 1600) * 4;  // 58,400 B
    cudaFuncSetAttribute(attn3_kernel, cudaFuncAttributeMaxDynamicSharedMemorySize, smem_bytes);

    attn3_kernel<<<dim3(8, 16, 4), 256, smem_bytes>>>(Wg, out);
}